// round 3
// baseline (speedup 1.0000x reference)
#include <cuda_runtime.h>
#include <math.h>

#define NUM_LEVELS 16
#define HASHMAP_SIZE (1u << 19)
#define HASH_MASK (HASHMAP_SIZE - 1u)
#define PRIME_Y 2654435761u
#define PRIME_Z 805459861u

struct Params {
    float scale[NUM_LEVELS];
    int   res[NUM_LEVELS];
    unsigned hashed;  // bitmask: level uses spatial hash
};

__global__ void __launch_bounds__(256) hashgrid_enc_kernel(
    const float* __restrict__ coords,
    const float2* __restrict__ table,
    float2* __restrict__ out,
    int n_points, Params P)
{
    long long total = (long long)n_points * NUM_LEVELS;
    long long stride = (long long)gridDim.x * 256;
    for (long long tid = blockIdx.x * 256LL + threadIdx.x; tid < total; tid += stride) {
        int level = (int)(tid & (NUM_LEVELS - 1));
        int p     = (int)(tid >> 4);

        const float* cp = coords + (size_t)p * 3;
        float x = __ldg(cp + 0);
        float y = __ldg(cp + 1);
        float z = __ldg(cp + 2);

        float scale = P.scale[level];
        int   res   = P.res[level];

        float px = fmaf(x, scale, 0.5f);
        float py = fmaf(y, scale, 0.5f);
        float pz = fmaf(z, scale, 0.5f);
        float gx = floorf(px), gy = floorf(py), gz = floorf(pz);
        float fx = px - gx,    fy = py - gy,    fz = pz - gz;
        int ix = (int)gx, iy = (int)gy, iz = (int)gz;

        unsigned idx[8];
        if ((P.hashed >> level) & 1u) {
            // spatial hash: (x*1) ^ (y*P1) ^ (z*P2), masked
            unsigned hx0 = (unsigned)ix,            hx1 = hx0 + 1u;
            unsigned hy0 = (unsigned)iy * PRIME_Y,  hy1 = hy0 + PRIME_Y;
            unsigned hz0 = (unsigned)iz * PRIME_Z,  hz1 = hz0 + PRIME_Z;
            idx[0] = (hx0 ^ hy0 ^ hz0) & HASH_MASK;
            idx[1] = (hx1 ^ hy0 ^ hz0) & HASH_MASK;
            idx[2] = (hx0 ^ hy1 ^ hz0) & HASH_MASK;
            idx[3] = (hx1 ^ hy1 ^ hz0) & HASH_MASK;
            idx[4] = (hx0 ^ hy0 ^ hz1) & HASH_MASK;
            idx[5] = (hx1 ^ hy0 ^ hz1) & HASH_MASK;
            idx[6] = (hx0 ^ hy1 ^ hz1) & HASH_MASK;
            idx[7] = (hx1 ^ hy1 ^ hz1) & HASH_MASK;
        } else {
            // dense grid: clip to [0, res-1], stride indexing
            int rm = res - 1;
            int r2 = res * res;
            int x0 = min(max(ix,     0), rm);
            int x1 = min(max(ix + 1, 0), rm);
            int y0 = min(max(iy,     0), rm) * res;
            int y1 = min(max(iy + 1, 0), rm) * res;
            int z0 = min(max(iz,     0), rm) * r2;
            int z1 = min(max(iz + 1, 0), rm) * r2;
            idx[0] = (unsigned)(x0 + y0 + z0);
            idx[1] = (unsigned)(x1 + y0 + z0);
            idx[2] = (unsigned)(x0 + y1 + z0);
            idx[3] = (unsigned)(x1 + y1 + z0);
            idx[4] = (unsigned)(x0 + y0 + z1);
            idx[5] = (unsigned)(x1 + y0 + z1);
            idx[6] = (unsigned)(x0 + y1 + z1);
            idx[7] = (unsigned)(x1 + y1 + z1);
        }

        const float2* tbl = table + (size_t)level * HASHMAP_SIZE;
        float2 f[8];
        #pragma unroll
        for (int i = 0; i < 8; i++) f[i] = __ldg(&tbl[idx[i]]);

        float wx0 = 1.0f - fx, wy0 = 1.0f - fy, wz0 = 1.0f - fz;
        float s0 = 0.0f, s1 = 0.0f;
        #pragma unroll
        for (int i = 0; i < 8; i++) {
            float w = ((i & 1) ? fx : wx0) * ((i & 2) ? fy : wy0) * ((i & 4) ? fz : wz0);
            s0 = fmaf(w, f[i].x, s0);
            s1 = fmaf(w, f[i].y, s1);
        }

        out[(size_t)p * NUM_LEVELS + level] = make_float2(s0, s1);
    }
}

extern "C" void kernel_launch(void* const* d_in, const int* in_sizes, int n_in,
                              void* d_out, int out_size)
{
    const float*  coords = (const float*)d_in[0];
    const float2* table  = (const float2*)d_in[1];
    float2*       out    = (float2*)d_out;
    int n_points = in_sizes[0] / 3;

    Params P;
    const double l2s = log2(1.3819);
    unsigned hashed = 0;
    for (int l = 0; l < NUM_LEVELS; l++) {
        double scale = exp2((double)l * l2s) * 16.0 - 1.0;
        int res = (int)ceil(scale) + 1;
        P.scale[l] = (float)scale;
        P.res[l]   = res;
        if ((long long)res * res * res > (long long)HASHMAP_SIZE) hashed |= (1u << l);
    }
    P.hashed = hashed;

    long long total = (long long)n_points * NUM_LEVELS;
    long long blocks = (total + 255) / 256;
    if (blocks > 2147483647LL) blocks = 2147483647LL;
    hashgrid_enc_kernel<<<(int)blocks, 256>>>(coords, table, out, n_points, P);
}

// round 5
// speedup vs baseline: 1.3557x; 1.3557x over previous
#include <cuda_runtime.h>
#include <math.h>

#define NUM_LEVELS 16
#define HASHMAP_SIZE (1u << 19)
#define HASH_MASK (HASHMAP_SIZE - 1u)
#define PRIME_Y 2654435761u
#define PRIME_Z 805459861u

struct Params {
    float scale[NUM_LEVELS];
    int   res[NUM_LEVELS];
    unsigned hashed;  // bitmask: level uses spatial hash
};

__global__ void __launch_bounds__(256) hashgrid_enc_kernel(
    const float* __restrict__ coords,
    const float2* __restrict__ table,
    float2* __restrict__ out,
    int n_points, Params P)
{
    long long total = (long long)n_points * NUM_LEVELS;
    long long tid = blockIdx.x * 256LL + threadIdx.x;
    if (tid >= total) return;

    int level = (int)(tid & (NUM_LEVELS - 1));
    int p     = (int)(tid >> 4);

    const float* cp = coords + (size_t)p * 3;
    float x = __ldg(cp + 0);
    float y = __ldg(cp + 1);
    float z = __ldg(cp + 2);

    float scale = P.scale[level];
    int   res   = P.res[level];

    float px = fmaf(x, scale, 0.5f);
    float py = fmaf(y, scale, 0.5f);
    float pz = fmaf(z, scale, 0.5f);
    float gx = floorf(px), gy = floorf(py), gz = floorf(pz);
    float fx = px - gx,    fy = py - gy,    fz = pz - gz;
    int ix = (int)gx, iy = (int)gy, iz = (int)gz;

    const float2* __restrict__ tbl = table + (size_t)level * HASHMAP_SIZE;

    // f[i]: corner i, bit0 = x, bit1 = y, bit2 = z
    float2 f[8];

    if ((P.hashed >> level) & 1u) {
        unsigned hx = (unsigned)ix;
        unsigned hy0 = (unsigned)iy * PRIME_Y, hy1 = hy0 + PRIME_Y;
        unsigned hz0 = (unsigned)iz * PRIME_Z, hz1 = hz0 + PRIME_Z;
        unsigned sv[4] = {hy0 ^ hz0, hy1 ^ hz0, hy0 ^ hz1, hy1 ^ hz1};

        if ((hx & 1u) == 0u) {
            // x even: h(x+1) = h(x) ^ 1 -> each x-pair lives in one aligned 16B entry pair
            #pragma unroll
            for (int j = 0; j < 4; j++) {
                unsigned u = (hx ^ sv[j]) & HASH_MASK;
                float4 v = __ldg((const float4*)(tbl + (u & ~1u)));
                float2 lo = make_float2(v.x, v.y);
                float2 hi = make_float2(v.z, v.w);
                bool odd = (u & 1u) != 0u;
                f[2*j]     = odd ? hi : lo;   // corner (x0) -> index u
                f[2*j + 1] = odd ? lo : hi;   // corner (x1) -> index u^1
            }
        } else {
            unsigned hx1 = hx + 1u;
            #pragma unroll
            for (int j = 0; j < 4; j++) {
                f[2*j]     = __ldg(tbl + ((hx  ^ sv[j]) & HASH_MASK));
                f[2*j + 1] = __ldg(tbl + ((hx1 ^ sv[j]) & HASH_MASK));
            }
        }
    } else {
        int rm = res - 1;
        int r2 = res * res;
        int x0 = min(max(ix,     0), rm);
        int x1 = min(max(ix + 1, 0), rm);
        int yb0 = min(max(iy,     0), rm) * res;
        int yb1 = min(max(iy + 1, 0), rm) * res;
        int zb0 = min(max(iz,     0), rm) * r2;
        int zb1 = min(max(iz + 1, 0), rm) * r2;
        int yz[4] = {yb0 + zb0, yb1 + zb0, yb0 + zb1, yb1 + zb1};
        bool adj = (x1 == x0 + 1);
        #pragma unroll
        for (int j = 0; j < 4; j++) {
            int i0 = x0 + yz[j];
            if (adj && ((i0 & 1) == 0)) {
                // entries i0, i0+1 in one aligned 16B pair
                float4 v = __ldg((const float4*)(tbl + i0));
                f[2*j]     = make_float2(v.x, v.y);
                f[2*j + 1] = make_float2(v.z, v.w);
            } else {
                f[2*j]     = __ldg(tbl + i0);
                f[2*j + 1] = __ldg(tbl + (x1 + yz[j]));
            }
        }
    }

    float wx0 = 1.0f - fx, wy0 = 1.0f - fy, wz0 = 1.0f - fz;
    float s0 = 0.0f, s1 = 0.0f;
    #pragma unroll
    for (int i = 0; i < 8; i++) {
        float w = ((i & 1) ? fx : wx0) * ((i & 2) ? fy : wy0) * ((i & 4) ? fz : wz0);
        s0 = fmaf(w, f[i].x, s0);
        s1 = fmaf(w, f[i].y, s1);
    }

    out[(size_t)p * NUM_LEVELS + level] = make_float2(s0, s1);
}

extern "C" void kernel_launch(void* const* d_in, const int* in_sizes, int n_in,
                              void* d_out, int out_size)
{
    const float*  coords = (const float*)d_in[0];
    const float2* table  = (const float2*)d_in[1];
    float2*       out    = (float2*)d_out;
    int n_points = in_sizes[0] / 3;

    Params P;
    const double l2s = log2(1.3819);
    unsigned hashed = 0;
    for (int l = 0; l < NUM_LEVELS; l++) {
        double scale = exp2((double)l * l2s) * 16.0 - 1.0;
        int res = (int)ceil(scale) + 1;
        P.scale[l] = (float)scale;
        P.res[l]   = res;
        if ((long long)res * res * res > (long long)HASHMAP_SIZE) hashed |= (1u << l);
    }
    P.hashed = hashed;

    long long total = (long long)n_points * NUM_LEVELS;
    long long blocks = (total + 255) / 256;
    hashgrid_enc_kernel<<<(int)blocks, 256>>>(coords, table, out, n_points, P);
}